// round 13
// baseline (speedup 1.0000x reference)
#include <cuda_runtime.h>

// ---------------------------------------------------------------------------
// DataReUploadingLinear, Round 9:
//  * cmm: 4x4 output tile + blocked 2-way k-split on lane bit 0.
//    Crossbar traffic 1.0MB/cmm (was 1.5MB for all 2x4/4x2 variants) ->
//    ~5.1K cyc, below the 8.2K FFMA2 floor. 24 u64 accumulators (48 regs),
//    static addressing, shfl_xor(1) combine, G added at store time.
//  * expm: s=6 + degree-16 Paterson-Stockmeyer (12 matmuls).
//  * Persistent CTAs + fused circuit via flag spin.
// ---------------------------------------------------------------------------

#define DIM      64
#define NPAULI   4096
#define S        68                  // smem row stride (rows 16B-aligned)
#define PL       (64 * S)            // plane floats (4352)
#define NTHREADS 512
#define INV_SCALE (1.0f / 64.0f)     // 1 / 2^s, s = 6
#define GRID     152

typedef unsigned long long u64;

__device__ float2 g_Up[4][DIM * DIM];
__device__ int    g_flag;            // finished param jobs
__device__ int    g_ctr;             // persistent job counter

__device__ __forceinline__ u64 pk2(float lo, float hi) {
    u64 r; asm("mov.b64 %0, {%1, %2};" : "=l"(r) : "f"(lo), "f"(hi)); return r;
}
__device__ __forceinline__ u64 f2fma(u64 a, u64 b, u64 c) {
    u64 d; asm("fma.rn.f32x2 %0, %1, %2, %3;" : "=l"(d) : "l"(a), "l"(b), "l"(c));
    return d;
}
__device__ __forceinline__ u64 f2add(u64 a, u64 b) {
    u64 d; asm("add.rn.f32x2 %0, %1, %2;" : "=l"(d) : "l"(a), "l"(b));
    return d;
}
__device__ __forceinline__ u64 f2sub(u64 a, u64 b) {
    float al, ah, bl, bh;
    asm("mov.b64 {%0, %1}, %2;" : "=f"(al), "=f"(ah) : "l"(a));
    asm("mov.b64 {%0, %1}, %2;" : "=f"(bl), "=f"(bh) : "l"(b));
    return pk2(al - bl, ah - bh);
}

// Z = [G(A)] + X*Y, complex 64x64 in smem planes (stride S). 512 threads.
// Tile: 4 rows x 4 cols per (ty,tx); k split in halves over klane = tid&1.
// tid bits: klane=tid&1, tx=(tid>>1)&15 -> j0=4*tx, ty=tid>>5 -> i0=4*ty.
// Combine halves via shfl_xor(1); lane with klane==p stores colpair p.
template <bool WITHG>
__device__ __forceinline__ void cmm(
    const float* __restrict__ Xr, const float* __restrict__ Xi,
    const float* __restrict__ Yr, const float* __restrict__ Yi,
    float* __restrict__ Zr, float* __restrict__ Zi,
    const float* __restrict__ Ar, const float* __restrict__ Ai,
    const float* __restrict__ A2r, const float* __restrict__ A2i,
    const float* __restrict__ A3r, const float* __restrict__ A3i,
    float c0, float c1, float c2, float c3)
{
    const int tid   = threadIdx.x;
    const int klane = tid & 1;
    const int tx    = (tid >> 1) & 15;
    const int ty    = tid >> 5;
    const int i0    = ty * 4;
    const int j0    = tx * 4;
    const int kbase = klane * 32;

    u64 crp[4][2], crn[4][2], cim[4][2];
#pragma unroll
    for (int a = 0; a < 4; a++)
#pragma unroll
        for (int p = 0; p < 2; p++) {
            crp[a][p] = 0ull; crn[a][p] = 0ull; cim[a][p] = 0ull;
        }

#pragma unroll 2
    for (int k2 = 0; k2 < 32; k2 += 2) {
        const int kg = kbase + k2;
        // X: 2 k's per row, broadcast within half-warp groups
        float2 xr2[4], xi2[4];
#pragma unroll
        for (int a = 0; a < 4; a++) {
            xr2[a] = *(const float2*)&Xr[(i0 + a) * S + kg];
            xi2[a] = *(const float2*)&Xi[(i0 + a) * S + kg];
        }
#pragma unroll
        for (int kk = 0; kk < 2; kk++) {
            const int row = kg + kk;
            const ulonglong2 r2 = *(const ulonglong2*)&Yr[row * S + j0];
            const ulonglong2 q2 = *(const ulonglong2*)&Yi[row * S + j0];
            const u64 yr[2] = { r2.x, r2.y };
            const u64 yi[2] = { q2.x, q2.y };
#pragma unroll
            for (int a = 0; a < 4; a++) {
                const float xr = kk ? xr2[a].y : xr2[a].x;
                const float xi = kk ? xi2[a].y : xi2[a].x;
                const u64 xrr = pk2(xr, xr);
                const u64 xii = pk2(xi, xi);
#pragma unroll
                for (int p = 0; p < 2; p++) {
                    crp[a][p] = f2fma(xrr, yr[p], crp[a][p]);
                    crn[a][p] = f2fma(xii, yi[p], crn[a][p]);
                    cim[a][p] = f2fma(xrr, yi[p], cim[a][p]);
                    cim[a][p] = f2fma(xii, yr[p], cim[a][p]);
                }
            }
        }
    }

    // combine the two k-halves; lane with klane==p stores colpair p
    const int jc = j0 + 2 * klane;
#pragma unroll
    for (int a = 0; a < 4; a++) {
        u64 v0 = f2sub(crp[a][0], crn[a][0]);
        u64 v1 = f2sub(crp[a][1], crn[a][1]);
        v0 = f2add(v0, __shfl_xor_sync(0xffffffffu, v0, 1));
        v1 = f2add(v1, __shfl_xor_sync(0xffffffffu, v1, 1));
        u64 w0 = f2add(cim[a][0], __shfl_xor_sync(0xffffffffu, cim[a][0], 1));
        u64 w1 = f2add(cim[a][1], __shfl_xor_sync(0xffffffffu, cim[a][1], 1));
        u64 vr = klane ? v1 : v0;
        u64 vi = klane ? w1 : w0;
        if (WITHG) {
            const int i = i0 + a;
            const int o0 = i * S + jc, o1 = o0 + 1;
            float g0r = c1 * Ar[o0] + c2 * A2r[o0] + c3 * A3r[o0]
                      + ((i == jc)     ? c0 : 0.f);
            float g1r = c1 * Ar[o1] + c2 * A2r[o1] + c3 * A3r[o1]
                      + ((i == jc + 1) ? c0 : 0.f);
            float g0i = c1 * Ai[o0] + c2 * A2i[o0] + c3 * A3i[o0];
            float g1i = c1 * Ai[o1] + c2 * A2i[o1] + c3 * A3i[o1];
            vr = f2add(vr, pk2(g0r, g1r));
            vi = f2add(vi, pk2(g0i, g1i));
        }
        *(u64*)&Zr[(i0 + a) * S + jc] = vr;
        *(u64*)&Zi[(i0 + a) * S + jc] = vi;
    }
}

__global__ void reset_kernel() { g_flag = 0; g_ctr = 0; }

// Persistent: job < nreps -> build Up[job]; else build Ud for sample
// (job - nreps), wait for all Up, run circuit, write out.
__global__ __launch_bounds__(NTHREADS, 1)
void build_kernel(const float* __restrict__ x,
                  const float* __restrict__ weight,
                  const float* __restrict__ bias,
                  float* __restrict__ out,
                  int nreps, int njobs)
{
    extern __shared__ float sm[];
    float* Ar  = sm + 0 * PL;  float* Ai  = sm + 1 * PL;
    float* A2r = sm + 2 * PL;  float* A2i = sm + 3 * PL;
    float* A3r = sm + 4 * PL;  float* A3i = sm + 5 * PL;
    float* A4r = sm + 6 * PL;  float* A4i = sm + 7 * PL;
    float* Br  = sm + 8 * PL;  float* Bi  = sm + 9 * PL;
    float* Cr  = sm + 10 * PL; float* Ci  = sm + 11 * PL;
    __shared__ float2 psiA[DIM], psiB[DIM];
    __shared__ int s_job;

    const int tid = threadIdx.x;

    for (;;) {
        __syncthreads();                    // smem reuse + s_job protect
        if (tid == 0) s_job = atomicAdd(&g_ctr, 1);
        __syncthreads();
        const int job = s_job;
        if (job >= njobs) return;
        const bool is_param = (job < nreps);

        // ---- 1. Pauli coefficients into Br[0..4095] ----
        if (is_param) {
            const float* wrow = weight + (size_t)job * (NPAULI - 1);
            for (int p = tid; p < NPAULI; p += NTHREADS)
                Br[p] = (p == 0) ? 0.f : wrow[p - 1];
        } else {
            const float* xrow = x + (size_t)(job - nreps) * 4000;
            for (int p = tid; p < NPAULI; p += NTHREADS)
                Br[p] = (p < 4000) ? xrow[p] : 0.f;
        }
        __syncthreads();

        // ---- 2. D[m][t] = coef(p(m,t)) * (-i)^popc(t&m) ----
        for (int idx = tid; idx < NPAULI; idx += NTHREADS) {
            const int m = idx >> 6, t = idx & 63;
            const int mt = m ^ t;
            int p = 0;
#pragma unroll
            for (int k = 0; k < 6; k++)
                p |= (((mt >> k) & 1) << (2 * k)) | (((t >> k) & 1) << (2 * k + 1));
            const float v = Br[p];
            const int c = __popc(t & m) & 3;
            float re, im;
            switch (c) {
                case 0:  re =  v; im = 0.f; break;
                case 1:  re = 0.f; im = -v; break;
                case 2:  re = -v; im = 0.f; break;
                default: re = 0.f; im =  v; break;
            }
            Cr[idx] = re; Ci[idx] = im;
        }
        __syncthreads();

        // ---- 3. 64-pt WHT over t for each m ----
        for (int s = 0; s < 6; s++) {
            const int half = 1 << s;
            for (int n = tid; n < 2048; n += NTHREADS) {
                const int m = n >> 5, r = n & 31;
                const int t0 = ((r >> s) << (s + 1)) | (r & (half - 1));
                const int a0 = m * 64 + t0, a1 = a0 + half;
                const float ur = Cr[a0], ui = Ci[a0];
                const float vr = Cr[a1], vi = Ci[a1];
                Cr[a0] = ur + vr; Ci[a0] = ui + vi;
                Cr[a1] = ur - vr; Ci[a1] = ui - vi;
            }
            __syncthreads();
        }

        // ---- 4. A = -i*H/2^s :  H[i][i^m] = W[m][i] ----
        for (int idx = tid; idx < NPAULI; idx += NTHREADS) {
            const int m = idx >> 6, i = idx & 63;
            const int j = i ^ m;
            const float hr = Cr[m * 64 + i], hi = Ci[m * 64 + i];
            Ar[i * S + j] =  hi * INV_SCALE;
            Ai[i * S + j] = -hr * INV_SCALE;
        }
        __syncthreads();

        // ---- 5. powers A2, A3, A4 ----
        cmm<false>(Ar, Ai, Ar, Ai, A2r, A2i,
                   Ar, Ai, A2r, A2i, A3r, A3i, 0, 0, 0, 0);
        __syncthreads();
        cmm<false>(Ar, Ai, A2r, A2i, A3r, A3i,
                   Ar, Ai, A2r, A2i, A3r, A3i, 0, 0, 0, 0);
        __syncthreads();
        cmm<false>(A2r, A2i, A2r, A2i, A4r, A4i,
                   Ar, Ai, A2r, A2i, A3r, A3i, 0, 0, 0, 0);
        __syncthreads();

        // ---- 6. degree-16 PS with A4 blocks ----
        {   // B = G3 = I/12! + A/13! + A2/14! + A3/15! + A4/16!
            const float c0 = 2.08767570e-9f,  d1 = 1.60590438e-10f;
            const float d2 = 1.14707456e-11f, d3 = 7.64716373e-13f;
            const float d4 = 4.77947733e-14f;
            for (int idx = tid; idx < NPAULI; idx += NTHREADS) {
                const int i = idx >> 6, j = idx & 63;
                const int o = i * S + j;
                float gr = d1 * Ar[o] + d2 * A2r[o] + d3 * A3r[o] + d4 * A4r[o];
                float gi = d1 * Ai[o] + d2 * A2i[o] + d3 * A3i[o] + d4 * A4i[o];
                if (i == j) gr += c0;
                Br[o] = gr; Bi[o] = gi;
            }
        }
        __syncthreads();
        // C = G2 + A4*B   (I/8! + A/9! + A2/10! + A3/11!)
        cmm<true>(A4r, A4i, Br, Bi, Cr, Ci, Ar, Ai, A2r, A2i, A3r, A3i,
                  2.48015873e-5f, 2.75573192e-6f, 2.75573192e-7f, 2.50521084e-8f);
        __syncthreads();
        // B = G1 + A4*C   (I/4! + A/5! + A2/6! + A3/7!)
        cmm<true>(A4r, A4i, Cr, Ci, Br, Bi, Ar, Ai, A2r, A2i, A3r, A3i,
                  4.16666667e-2f, 8.33333333e-3f, 1.38888889e-3f, 1.98412698e-4f);
        __syncthreads();
        // C = G0 + A4*B   (I + A + A2/2 + A3/6)
        cmm<true>(A4r, A4i, Br, Bi, Cr, Ci, Ar, Ai, A2r, A2i, A3r, A3i,
                  1.f, 1.f, 0.5f, 1.f / 6.f);
        __syncthreads();

        // ---- 7. 6 squarings, ping-pong C <-> B (ends in C) ----
        float *qr = Cr, *qi = Ci, *pr = Br, *pi = Bi;
#pragma unroll 1
        for (int q = 0; q < 6; q++) {
            cmm<false>(qr, qi, qr, qi, pr, pi,
                       Ar, Ai, A2r, A2i, A3r, A3i, 0, 0, 0, 0);
            __syncthreads();
            float* t;
            t = qr; qr = pr; pr = t;
            t = qi; qi = pi; pi = t;
        }

        // ---- 8a. parameter job: publish Up and signal ----
        if (is_param) {
            for (int idx = tid; idx < DIM * DIM; idx += NTHREADS) {
                const int i = idx >> 6, j = idx & 63;
                g_Up[job][idx] = make_float2(qr[i * S + j], qi[i * S + j]);
            }
            __threadfence();
            __syncthreads();
            if (tid == 0) atomicAdd(&g_flag, 1);
            continue;
        }

        // ---- 8b. data job: wait for Up, run circuit ----
        if (tid == 0) {
            int v;
            do {
                asm volatile("ld.global.acquire.gpu.b32 %0, [%1];"
                             : "=r"(v) : "l"(&g_flag));
                if (v < nreps) __nanosleep(64);
            } while (v < nreps);
        }
        __threadfence();
        if (tid < DIM) psiA[tid] = make_float2(tid == 0 ? 1.f : 0.f, 0.f);
        __syncthreads();

        if (tid < 256) {
            float2* pin = psiA;
            float2* pout = psiB;
            const int row = tid >> 2, part = tid & 3;
            const int k0 = part * 16;

            for (int r = 0; r < nreps; r++) {
                {   // pout = Ud * pin  (Ud in smem planes qr/qi)
                    float sr = 0.f, si = 0.f;
#pragma unroll
                    for (int k = k0; k < k0 + 16; k++) {
                        const float mr = qr[row * S + k], mi = qi[row * S + k];
                        const float2 v = pin[k];
                        sr = fmaf(mr, v.x, sr); sr = fmaf(-mi, v.y, sr);
                        si = fmaf(mr, v.y, si); si = fmaf(mi, v.x, si);
                    }
                    sr += __shfl_xor_sync(0xffffffffu, sr, 1);
                    sr += __shfl_xor_sync(0xffffffffu, sr, 2);
                    si += __shfl_xor_sync(0xffffffffu, si, 1);
                    si += __shfl_xor_sync(0xffffffffu, si, 2);
                    if (part == 0) pout[row] = make_float2(sr, si);
                }
                __syncwarp();
                asm volatile("bar.sync 1, 256;" ::: "memory");
                { float2* t = pin; pin = pout; pout = t; }

                {   // pout = Up[r] * pin
                    const float2* U = g_Up[r];
                    float sr = 0.f, si = 0.f;
#pragma unroll
                    for (int k = k0; k < k0 + 16; k++) {
                        const float2 u = U[row * DIM + k];
                        const float2 v = pin[k];
                        sr = fmaf(u.x, v.x, sr); sr = fmaf(-u.y, v.y, sr);
                        si = fmaf(u.x, v.y, si); si = fmaf(u.y, v.x, si);
                    }
                    sr += __shfl_xor_sync(0xffffffffu, sr, 1);
                    sr += __shfl_xor_sync(0xffffffffu, sr, 2);
                    si += __shfl_xor_sync(0xffffffffu, si, 1);
                    si += __shfl_xor_sync(0xffffffffu, si, 2);
                    if (part == 0) pout[row] = make_float2(sr, si);
                }
                __syncwarp();
                asm volatile("bar.sync 1, 256;" ::: "memory");
                { float2* t = pin; pin = pout; pout = t; }
            }

            if (tid < DIM) {
                const float2 v = pin[tid];
                out[(size_t)(job - nreps) * DIM + tid] =
                    fmaf(v.x, v.x, v.y * v.y) + bias[tid];
            }
        }
    }
}

extern "C" void kernel_launch(void* const* d_in, const int* in_sizes, int n_in,
                              void* d_out, int out_size)
{
    const float* x      = (const float*)d_in[0];   // [512, 4000]
    const float* weight = (const float*)d_in[1];   // [4, 4095]
    const float* bias   = (const float*)d_in[2];   // [64]
    float* out = (float*)d_out;                    // [512, 64]

    const int B     = in_sizes[0] / 4000;
    const int nreps = in_sizes[1] / (NPAULI - 1);
    const int njobs = nreps + B;

    const size_t smem = (size_t)12 * PL * sizeof(float);   // 208,896 B
    cudaFuncSetAttribute(build_kernel,
                         cudaFuncAttributeMaxDynamicSharedMemorySize, (int)smem);

    reset_kernel<<<1, 1>>>();
    const int grid = (njobs < GRID) ? njobs : GRID;
    build_kernel<<<grid, NTHREADS, smem>>>(x, weight, bias, out, nreps, njobs);
}

// round 15
// speedup vs baseline: 1.5906x; 1.5906x over previous
#include <cuda_runtime.h>

// ---------------------------------------------------------------------------
// DataReUploadingLinear, Round 13:
//   Champion (R3) cmm body + configuration, verbatim.
//   Matmul-count reduction: stop squaring at V = exp(-iH/4) (s=6, deg-16 PS,
//   4 squarings) -> 10 matmuls (was 13). Circuit applies V 4x per U via
//   cheap matvecs (4 reps x (4 Vd + 4 Vp) = 32 matvecs, 512-thread rows).
//   Param jobs publish Vp = Up^(1/4): identical schedule, no extra spin.
// ---------------------------------------------------------------------------

#define DIM      64
#define NPAULI   4096
#define S        68                  // smem row stride (rows 16B-aligned)
#define PL       (64 * S)            // plane floats (4352)
#define NTHREADS 512
#define INV_SCALE (1.0f / 64.0f)     // 1 / 2^s, s = 6
#define NSQ      4                   // stop early: V = exp(-iH/4)
#define VAPP     4                   // V applications per U
#define MAXB     512

typedef unsigned long long u64;

__device__ float2 g_Up[4][DIM * DIM];   // QUARTER-power parameter unitaries
__device__ int    g_flag;               // finished param jobs

__device__ __forceinline__ u64 pk2(float lo, float hi) {
    u64 r; asm("mov.b64 %0, {%1, %2};" : "=l"(r) : "f"(lo), "f"(hi)); return r;
}
__device__ __forceinline__ u64 f2fma(u64 a, u64 b, u64 c) {
    u64 d; asm("fma.rn.f32x2 %0, %1, %2, %3;" : "=l"(d) : "l"(a), "l"(b), "l"(c));
    return d;
}
__device__ __forceinline__ u64 f2sub(u64 a, u64 b) {
    float al, ah, bl, bh;
    asm("mov.b64 {%0, %1}, %2;" : "=f"(al), "=f"(ah) : "l"(a));
    asm("mov.b64 {%0, %1}, %2;" : "=f"(bl), "=f"(bh) : "l"(b));
    return pk2(al - bl, ah - bh);
}

// Z = [G(A)] + X*Y  (champion R3 body; G extended to c0 I + c1 A + c2 A2
// + c3 A3 for the deg-16 blocks). Tile 2 rows x 4 cols, 512 threads.
template <bool WITHG>
__device__ __forceinline__ void cmm(
    const float* __restrict__ Xr, const float* __restrict__ Xi,
    const float* __restrict__ Yr, const float* __restrict__ Yi,
    float* __restrict__ Zr, float* __restrict__ Zi,
    const float* __restrict__ Ar, const float* __restrict__ Ai,
    const float* __restrict__ A2r, const float* __restrict__ A2i,
    const float* __restrict__ A3r, const float* __restrict__ A3i,
    float c0, float c1, float c2, float c3)
{
    const int tid = threadIdx.x;
    const int ty = tid >> 4, tx = tid & 15;
    const int i0 = ty * 2, j0 = tx * 4;

    u64 crp[2][2], crn[2][2], cim[2][2];
#pragma unroll
    for (int a = 0; a < 2; a++)
#pragma unroll
        for (int p = 0; p < 2; p++) {
            if (WITHG) {
                const int i = i0 + a, j = j0 + 2 * p;
                const int o0 = i * S + j, o1 = o0 + 1;
                float g0r = c1 * Ar[o0] + c2 * A2r[o0] + c3 * A3r[o0]
                          + ((i == j)     ? c0 : 0.f);
                float g1r = c1 * Ar[o1] + c2 * A2r[o1] + c3 * A3r[o1]
                          + ((i == j + 1) ? c0 : 0.f);
                float g0i = c1 * Ai[o0] + c2 * A2i[o0] + c3 * A3i[o0];
                float g1i = c1 * Ai[o1] + c2 * A2i[o1] + c3 * A3i[o1];
                crp[a][p] = pk2(g0r, g1r);
                cim[a][p] = pk2(g0i, g1i);
            } else {
                crp[a][p] = 0ull; cim[a][p] = 0ull;
            }
            crn[a][p] = 0ull;
        }

#pragma unroll 2
    for (int k4 = 0; k4 < 64; k4 += 4) {
        // X: LDS.128 over 4 consecutive k (broadcast within half-warp)
        float4 xr4[2], xi4[2];
#pragma unroll
        for (int a = 0; a < 2; a++) {
            xr4[a] = *(const float4*)&Xr[(i0 + a) * S + k4];
            xi4[a] = *(const float4*)&Xi[(i0 + a) * S + k4];
        }
#pragma unroll
        for (int kk = 0; kk < 4; kk++) {
            const int row = k4 + kk;
            const ulonglong2 r2 = *(const ulonglong2*)&Yr[row * S + j0];
            const ulonglong2 q2 = *(const ulonglong2*)&Yi[row * S + j0];
            const u64 yr[2] = { r2.x, r2.y };
            const u64 yi[2] = { q2.x, q2.y };
#pragma unroll
            for (int a = 0; a < 2; a++) {
                const float xr = (kk == 0) ? xr4[a].x : (kk == 1) ? xr4[a].y
                               : (kk == 2) ? xr4[a].z : xr4[a].w;
                const float xi = (kk == 0) ? xi4[a].x : (kk == 1) ? xi4[a].y
                               : (kk == 2) ? xi4[a].z : xi4[a].w;
                const u64 xrr = pk2(xr, xr);
                const u64 xii = pk2(xi, xi);
#pragma unroll
                for (int p = 0; p < 2; p++) {
                    crp[a][p] = f2fma(xrr, yr[p], crp[a][p]);
                    crn[a][p] = f2fma(xii, yi[p], crn[a][p]);
                    cim[a][p] = f2fma(xrr, yi[p], cim[a][p]);
                    cim[a][p] = f2fma(xii, yr[p], cim[a][p]);
                }
            }
        }
    }

#pragma unroll
    for (int a = 0; a < 2; a++)
#pragma unroll
        for (int p = 0; p < 2; p++) {
            *(u64*)&Zr[(i0 + a) * S + j0 + 2 * p] = f2sub(crp[a][p], crn[a][p]);
            *(u64*)&Zi[(i0 + a) * S + j0 + 2 * p] = cim[a][p];
        }
}

__global__ void reset_kernel() { g_flag = 0; }

// blockIdx < nreps: build Vp[blk] = Up[blk]^(1/4) -> g_Up, signal.
// else: build Vd = Ud^(1/4) for sample (blk - nreps), wait, circuit, out.
__global__ __launch_bounds__(NTHREADS)
void build_kernel(const float* __restrict__ x,
                  const float* __restrict__ weight,
                  const float* __restrict__ bias,
                  float* __restrict__ out,
                  int nreps)
{
    extern __shared__ float sm[];
    float* Ar  = sm + 0 * PL;  float* Ai  = sm + 1 * PL;
    float* A2r = sm + 2 * PL;  float* A2i = sm + 3 * PL;
    float* A3r = sm + 4 * PL;  float* A3i = sm + 5 * PL;
    float* A4r = sm + 6 * PL;  float* A4i = sm + 7 * PL;
    float* Br  = sm + 8 * PL;  float* Bi  = sm + 9 * PL;
    float* Cr  = sm + 10 * PL; float* Ci  = sm + 11 * PL;
    __shared__ float2 psiA[DIM], psiB[DIM];

    const int tid = threadIdx.x;
    const int blk = blockIdx.x;
    const bool is_param = (blk < nreps);

    // ---- 1. Pauli coefficients into Br[0..4095] ----
    if (is_param) {
        const float* wrow = weight + (size_t)blk * (NPAULI - 1);
        for (int p = tid; p < NPAULI; p += NTHREADS)
            Br[p] = (p == 0) ? 0.f : wrow[p - 1];      // identity excluded
    } else {
        const float* xrow = x + (size_t)(blk - nreps) * 4000;
        for (int p = tid; p < NPAULI; p += NTHREADS)
            Br[p] = (p < 4000) ? xrow[p] : 0.f;
    }
    __syncthreads();

    // ---- 2. D[m][t] = coef(p(m,t)) * (-i)^popc(t&m) ----
    for (int idx = tid; idx < NPAULI; idx += NTHREADS) {
        const int m = idx >> 6, t = idx & 63;
        const int mt = m ^ t;
        int p = 0;
#pragma unroll
        for (int k = 0; k < 6; k++)
            p |= (((mt >> k) & 1) << (2 * k)) | (((t >> k) & 1) << (2 * k + 1));
        const float v = Br[p];
        const int c = __popc(t & m) & 3;   // (-i)^c
        float re, im;
        switch (c) {
            case 0:  re =  v; im = 0.f; break;
            case 1:  re = 0.f; im = -v; break;
            case 2:  re = -v; im = 0.f; break;
            default: re = 0.f; im =  v; break;
        }
        Cr[idx] = re; Ci[idx] = im;
    }
    __syncthreads();

    // ---- 3. 64-pt WHT over t for each m ----
    for (int s = 0; s < 6; s++) {
        const int half = 1 << s;
        for (int n = tid; n < 2048; n += NTHREADS) {
            const int m = n >> 5, r = n & 31;
            const int t0 = ((r >> s) << (s + 1)) | (r & (half - 1));
            const int a0 = m * 64 + t0, a1 = a0 + half;
            const float ur = Cr[a0], ui = Ci[a0];
            const float vr = Cr[a1], vi = Ci[a1];
            Cr[a0] = ur + vr; Ci[a0] = ui + vi;
            Cr[a1] = ur - vr; Ci[a1] = ui - vi;
        }
        __syncthreads();
    }

    // ---- 4. A = -i*H/2^s :  H[i][i^m] = W[m][i] ----
    for (int idx = tid; idx < NPAULI; idx += NTHREADS) {
        const int m = idx >> 6, i = idx & 63;
        const int j = i ^ m;
        const float hr = Cr[m * 64 + i], hi = Ci[m * 64 + i];
        Ar[i * S + j] =  hi * INV_SCALE;   // -i*(hr+i*hi) = hi - i*hr
        Ai[i * S + j] = -hr * INV_SCALE;
    }
    __syncthreads();

    // ---- 5. powers A2, A3, A4 ----
    cmm<false>(Ar, Ai, Ar, Ai, A2r, A2i,
               Ar, Ai, A2r, A2i, A3r, A3i, 0, 0, 0, 0);
    __syncthreads();
    cmm<false>(Ar, Ai, A2r, A2i, A3r, A3i,
               Ar, Ai, A2r, A2i, A3r, A3i, 0, 0, 0, 0);
    __syncthreads();
    cmm<false>(A2r, A2i, A2r, A2i, A4r, A4i,
               Ar, Ai, A2r, A2i, A3r, A3i, 0, 0, 0, 0);
    __syncthreads();

    // ---- 6. degree-16 PS with A4 blocks ----
    {   // B = G3 = I/12! + A/13! + A2/14! + A3/15! + A4/16!
        const float c0 = 2.08767570e-9f,  d1 = 1.60590438e-10f;
        const float d2 = 1.14707456e-11f, d3 = 7.64716373e-13f;
        const float d4 = 4.77947733e-14f;
        for (int idx = tid; idx < NPAULI; idx += NTHREADS) {
            const int i = idx >> 6, j = idx & 63;
            const int o = i * S + j;
            float gr = d1 * Ar[o] + d2 * A2r[o] + d3 * A3r[o] + d4 * A4r[o];
            float gi = d1 * Ai[o] + d2 * A2i[o] + d3 * A3i[o] + d4 * A4i[o];
            if (i == j) gr += c0;
            Br[o] = gr; Bi[o] = gi;
        }
    }
    __syncthreads();
    // C = G2 + A4*B   (I/8! + A/9! + A2/10! + A3/11!)
    cmm<true>(A4r, A4i, Br, Bi, Cr, Ci, Ar, Ai, A2r, A2i, A3r, A3i,
              2.48015873e-5f, 2.75573192e-6f, 2.75573192e-7f, 2.50521084e-8f);
    __syncthreads();
    // B = G1 + A4*C   (I/4! + A/5! + A2/6! + A3/7!)
    cmm<true>(A4r, A4i, Cr, Ci, Br, Bi, Ar, Ai, A2r, A2i, A3r, A3i,
              4.16666667e-2f, 8.33333333e-3f, 1.38888889e-3f, 1.98412698e-4f);
    __syncthreads();
    // C = G0 + A4*B   (I + A + A2/2 + A3/6)
    cmm<true>(A4r, A4i, Br, Bi, Cr, Ci, Ar, Ai, A2r, A2i, A3r, A3i,
              1.f, 1.f, 0.5f, 1.f / 6.f);
    __syncthreads();

    // ---- 7. NSQ=4 squarings, ping-pong C <-> B (even -> ends in C) ----
    // Result: V = exp(-i H / 4)
    float *qr = Cr, *qi = Ci, *pr = Br, *pi = Bi;
#pragma unroll 1
    for (int q = 0; q < NSQ; q++) {
        cmm<false>(qr, qi, qr, qi, pr, pi,
                   Ar, Ai, A2r, A2i, A3r, A3i, 0, 0, 0, 0);
        __syncthreads();
        float* t;
        t = qr; qr = pr; pr = t;
        t = qi; qi = pi; pi = t;
    }

    // ---- 8a. parameter job: publish Vp = Up^(1/4) and signal ----
    if (is_param) {
        for (int idx = tid; idx < DIM * DIM; idx += NTHREADS) {
            const int i = idx >> 6, j = idx & 63;
            g_Up[blk][idx] = make_float2(qr[i * S + j], qi[i * S + j]);
        }
        __threadfence();               // release g_Up before flag bump
        __syncthreads();
        if (tid == 0) atomicAdd(&g_flag, 1);
        return;
    }

    // ---- 8b. data job: wait for all Vp, run circuit ----
    if (tid == 0) {
        int v;
        do {
            asm volatile("ld.global.acquire.gpu.b32 %0, [%1];"
                         : "=r"(v) : "l"(&g_flag));
            if (v < nreps) __nanosleep(64);
        } while (v < nreps);
    }
    if (tid < DIM) psiA[tid] = make_float2(tid == 0 ? 1.f : 0.f, 0.f);
    __syncthreads();

    // matvec layout: 512 threads = 64 rows x 8 partials
    float2* pin = psiA;
    float2* pout = psiB;
    const int row = tid >> 3, part = tid & 7;
    const int k0 = part * 8;

    for (int r = 0; r < 4; r++) {
        // Ud = Vd^4 : apply Vd (smem planes qr/qi) VAPP times
#pragma unroll 1
        for (int v = 0; v < VAPP; v++) {
            float sr = 0.f, si = 0.f;
#pragma unroll
            for (int k = k0; k < k0 + 8; k++) {
                const float mr = qr[row * S + k], mi = qi[row * S + k];
                const float2 w = pin[k];
                sr = fmaf(mr, w.x, sr); sr = fmaf(-mi, w.y, sr);
                si = fmaf(mr, w.y, si); si = fmaf(mi, w.x, si);
            }
            sr += __shfl_xor_sync(0xffffffffu, sr, 1);
            sr += __shfl_xor_sync(0xffffffffu, sr, 2);
            sr += __shfl_xor_sync(0xffffffffu, sr, 4);
            si += __shfl_xor_sync(0xffffffffu, si, 1);
            si += __shfl_xor_sync(0xffffffffu, si, 2);
            si += __shfl_xor_sync(0xffffffffu, si, 4);
            if (part == 0) pout[row] = make_float2(sr, si);
            __syncthreads();
            { float2* t = pin; pin = pout; pout = t; }
        }
        // Up[r] = Vp^4 : apply Vp (global) VAPP times
        const float2* U = g_Up[r];
#pragma unroll 1
        for (int v = 0; v < VAPP; v++) {
            float sr = 0.f, si = 0.f;
#pragma unroll
            for (int k = k0; k < k0 + 8; k++) {
                const float2 u = U[row * DIM + k];
                const float2 w = pin[k];
                sr = fmaf(u.x, w.x, sr); sr = fmaf(-u.y, w.y, sr);
                si = fmaf(u.x, w.y, si); si = fmaf(u.y, w.x, si);
            }
            sr += __shfl_xor_sync(0xffffffffu, sr, 1);
            sr += __shfl_xor_sync(0xffffffffu, sr, 2);
            sr += __shfl_xor_sync(0xffffffffu, sr, 4);
            si += __shfl_xor_sync(0xffffffffu, si, 1);
            si += __shfl_xor_sync(0xffffffffu, si, 2);
            si += __shfl_xor_sync(0xffffffffu, si, 4);
            if (part == 0) pout[row] = make_float2(sr, si);
            __syncthreads();
            { float2* t = pin; pin = pout; pout = t; }
        }
    }

    if (tid < DIM) {
        const float2 v = pin[tid];
        out[(size_t)(blk - nreps) * DIM + tid] =
            fmaf(v.x, v.x, v.y * v.y) + bias[tid];
    }
}

extern "C" void kernel_launch(void* const* d_in, const int* in_sizes, int n_in,
                              void* d_out, int out_size)
{
    const float* x      = (const float*)d_in[0];   // [512, 4000]
    const float* weight = (const float*)d_in[1];   // [4, 4095]
    const float* bias   = (const float*)d_in[2];   // [64]
    float* out = (float*)d_out;                    // [512, 64]

    const int B     = in_sizes[0] / 4000;
    const int nreps = in_sizes[1] / (NPAULI - 1);

    const size_t smem = (size_t)12 * PL * sizeof(float);   // 208,896 B
    cudaFuncSetAttribute(build_kernel,
                         cudaFuncAttributeMaxDynamicSharedMemorySize, (int)smem);

    reset_kernel<<<1, 1>>>();
    build_kernel<<<nreps + B, NTHREADS, smem>>>(x, weight, bias, out, nreps);
}

// round 16
// speedup vs baseline: 1.6261x; 1.0223x over previous
#include <cuda_runtime.h>

// ---------------------------------------------------------------------------
// DataReUploadingLinear, Round 15: occupancy-2 redesign.
//  * 3 complex smem planes only (A, A2, W = 104.4KB) -> 2 CTAs/SM.
//    - in-place cmm: barrier between read phase and writeback, Z may alias.
//    - s=8 + degree-7 Taylor in A2 blocks: 1 power + 3 Horner muls.
//    - V-trick (verified R13): stop at 6 squarings -> V=exp(-iH/4), 4 apps.
//    => 10 cmms total, champion (R3) cmm inner loop, float2 X loads.
//  * __launch_bounds__(512, 2), persistent grid = 2*152 CTAs.
// ---------------------------------------------------------------------------

#define DIM      64
#define NPAULI   4096
#define S        68                  // smem row stride (rows 16B-aligned)
#define PL       (64 * S)            // plane floats (4352)
#define NTHREADS 512
#define INV_SCALE (1.0f / 256.0f)    // 1 / 2^s, s = 8
#define NSQ      6                   // A->V: 6 squarings, V = exp(-iH/4)
#define VAPP     4                   // V applications per U
#define GRID     304                 // 2 CTAs x 152 SMs, all resident

typedef unsigned long long u64;

__device__ float2 g_Up[4][DIM * DIM];   // quarter-power parameter unitaries
__device__ int    g_flag;               // finished param jobs
__device__ int    g_ctr;                // persistent job counter

__device__ __forceinline__ u64 pk2(float lo, float hi) {
    u64 r; asm("mov.b64 %0, {%1, %2};" : "=l"(r) : "f"(lo), "f"(hi)); return r;
}
__device__ __forceinline__ u64 f2fma(u64 a, u64 b, u64 c) {
    u64 d; asm("fma.rn.f32x2 %0, %1, %2, %3;" : "=l"(d) : "l"(a), "l"(b), "l"(c));
    return d;
}
__device__ __forceinline__ u64 f2sub(u64 a, u64 b) {
    float al, ah, bl, bh;
    asm("mov.b64 {%0, %1}, %2;" : "=f"(al), "=f"(ah) : "l"(a));
    asm("mov.b64 {%0, %1}, %2;" : "=f"(bl), "=f"(bh) : "l"(b));
    return pk2(al - bl, ah - bh);
}

// Z = [c0 I + c1 A] + X*Y, complex 64x64 in smem planes (stride S).
// 512 threads, tile 2 rows x 4 cols (champion R3 body, float2 X loads).
// INPLACE: __syncthreads() before writeback so Z may alias X and/or Y.
template <bool WITHG, bool INPLACE>
__device__ __forceinline__ void cmm(
    const float* __restrict__ Xr, const float* __restrict__ Xi,
    const float* __restrict__ Yr, const float* __restrict__ Yi,
    float* __restrict__ Zr, float* __restrict__ Zi,
    const float* __restrict__ Ar, const float* __restrict__ Ai,
    float c0, float c1)
{
    const int tid = threadIdx.x;
    const int ty = tid >> 4, tx = tid & 15;
    const int i0 = ty * 2, j0 = tx * 4;

    u64 crp[2][2], crn[2][2], cim[2][2];
#pragma unroll
    for (int a = 0; a < 2; a++)
#pragma unroll
        for (int p = 0; p < 2; p++) {
            if (WITHG) {
                const int i = i0 + a, j = j0 + 2 * p;
                const int o0 = i * S + j, o1 = o0 + 1;
                float g0r = c1 * Ar[o0] + ((i == j)     ? c0 : 0.f);
                float g1r = c1 * Ar[o1] + ((i == j + 1) ? c0 : 0.f);
                crp[a][p] = pk2(g0r, g1r);
                cim[a][p] = pk2(c1 * Ai[o0], c1 * Ai[o1]);
            } else {
                crp[a][p] = 0ull; cim[a][p] = 0ull;
            }
            crn[a][p] = 0ull;
        }

#pragma unroll 2
    for (int k0 = 0; k0 < 64; k0 += 2) {
        float2 xr2[2], xi2[2];
#pragma unroll
        for (int a = 0; a < 2; a++) {
            xr2[a] = *(const float2*)&Xr[(i0 + a) * S + k0];
            xi2[a] = *(const float2*)&Xi[(i0 + a) * S + k0];
        }
#pragma unroll
        for (int kk = 0; kk < 2; kk++) {
            const int row = k0 + kk;
            const ulonglong2 r2 = *(const ulonglong2*)&Yr[row * S + j0];
            const ulonglong2 q2 = *(const ulonglong2*)&Yi[row * S + j0];
            const u64 yr[2] = { r2.x, r2.y };
            const u64 yi[2] = { q2.x, q2.y };
#pragma unroll
            for (int a = 0; a < 2; a++) {
                const float xr = kk ? xr2[a].y : xr2[a].x;
                const float xi = kk ? xi2[a].y : xi2[a].x;
                const u64 xrr = pk2(xr, xr);
                const u64 xii = pk2(xi, xi);
#pragma unroll
                for (int p = 0; p < 2; p++) {
                    crp[a][p] = f2fma(xrr, yr[p], crp[a][p]);
                    crn[a][p] = f2fma(xii, yi[p], crn[a][p]);
                    cim[a][p] = f2fma(xrr, yi[p], cim[a][p]);
                    cim[a][p] = f2fma(xii, yr[p], cim[a][p]);
                }
            }
        }
    }

    if (INPLACE) __syncthreads();       // all reads done before any write

#pragma unroll
    for (int a = 0; a < 2; a++)
#pragma unroll
        for (int p = 0; p < 2; p++) {
            *(u64*)&Zr[(i0 + a) * S + j0 + 2 * p] = f2sub(crp[a][p], crn[a][p]);
            *(u64*)&Zi[(i0 + a) * S + j0 + 2 * p] = cim[a][p];
        }
}

__global__ void reset_kernel() { g_flag = 0; g_ctr = 0; }

// Persistent: job < nreps -> publish Vp[job]=Up^(1/4); else build Vd for
// sample (job-nreps), wait for all Vp, run circuit (V applied 4x per U).
__global__ __launch_bounds__(NTHREADS, 2)
void build_kernel(const float* __restrict__ x,
                  const float* __restrict__ weight,
                  const float* __restrict__ bias,
                  float* __restrict__ out,
                  int nreps, int njobs)
{
    extern __shared__ float sm[];
    float* Ar  = sm + 0 * PL;  float* Ai  = sm + 1 * PL;
    float* A2r = sm + 2 * PL;  float* A2i = sm + 3 * PL;
    float* Wr  = sm + 4 * PL;  float* Wi  = sm + 5 * PL;
    __shared__ float2 psiA[DIM], psiB[DIM];
    __shared__ int s_job;

    const int tid = threadIdx.x;

    for (;;) {
        __syncthreads();                    // smem reuse + s_job protect
        if (tid == 0) s_job = atomicAdd(&g_ctr, 1);
        __syncthreads();
        const int job = s_job;
        if (job >= njobs) return;
        const bool is_param = (job < nreps);

        // ---- 1. Pauli coefficients into A2r[0..4095] (scratch) ----
        if (is_param) {
            const float* wrow = weight + (size_t)job * (NPAULI - 1);
            for (int p = tid; p < NPAULI; p += NTHREADS)
                A2r[p] = (p == 0) ? 0.f : wrow[p - 1];   // identity excluded
        } else {
            const float* xrow = x + (size_t)(job - nreps) * 4000;
            for (int p = tid; p < NPAULI; p += NTHREADS)
                A2r[p] = (p < 4000) ? xrow[p] : 0.f;
        }
        __syncthreads();

        // ---- 2. D[m][t] = coef(p(m,t)) * (-i)^popc(t&m) -> W planes ----
        for (int idx = tid; idx < NPAULI; idx += NTHREADS) {
            const int m = idx >> 6, t = idx & 63;
            const int mt = m ^ t;
            int p = 0;
#pragma unroll
            for (int k = 0; k < 6; k++)
                p |= (((mt >> k) & 1) << (2 * k)) | (((t >> k) & 1) << (2 * k + 1));
            const float v = A2r[p];
            const int c = __popc(t & m) & 3;   // (-i)^c
            float re, im;
            switch (c) {
                case 0:  re =  v; im = 0.f; break;
                case 1:  re = 0.f; im = -v; break;
                case 2:  re = -v; im = 0.f; break;
                default: re = 0.f; im =  v; break;
            }
            Wr[idx] = re; Wi[idx] = im;
        }
        __syncthreads();

        // ---- 3. 64-pt WHT over t for each m ----
        for (int s = 0; s < 6; s++) {
            const int half = 1 << s;
            for (int n = tid; n < 2048; n += NTHREADS) {
                const int m = n >> 5, r = n & 31;
                const int t0 = ((r >> s) << (s + 1)) | (r & (half - 1));
                const int a0 = m * 64 + t0, a1 = a0 + half;
                const float ur = Wr[a0], ui = Wi[a0];
                const float vr = Wr[a1], vi = Wi[a1];
                Wr[a0] = ur + vr; Wi[a0] = ui + vi;
                Wr[a1] = ur - vr; Wi[a1] = ui - vi;
            }
            __syncthreads();
        }

        // ---- 4. A = -i*H/2^8 :  H[i][i^m] = W[m][i] ----
        for (int idx = tid; idx < NPAULI; idx += NTHREADS) {
            const int m = idx >> 6, i = idx & 63;
            const int j = i ^ m;
            const float hr = Wr[m * 64 + i], hi = Wi[m * 64 + i];
            Ar[i * S + j] =  hi * INV_SCALE;   // -i*(hr+i*hi) = hi - i*hr
            Ai[i * S + j] = -hr * INV_SCALE;
        }
        __syncthreads();

        // ---- 5. A2 = A*A  (distinct dst, no in-place barrier needed) ----
        cmm<false, false>(Ar, Ai, Ar, Ai, A2r, A2i, Ar, Ai, 0, 0);
        __syncthreads();

        // ---- 6. degree-7 Taylor, Horner in A2 blocks, all in W ----
        // W = G3 = I/720 + A/5040   (elementwise)
        for (int idx = tid; idx < NPAULI; idx += NTHREADS) {
            const int i = idx >> 6, j = idx & 63;
            const int o = i * S + j;
            Wr[o] = 1.98412698e-4f * Ar[o] + ((i == j) ? 1.38888889e-3f : 0.f);
            Wi[o] = 1.98412698e-4f * Ai[o];
        }
        __syncthreads();
        // W = G2 + A2*W   (I/24 + A/120)
        cmm<true, true>(A2r, A2i, Wr, Wi, Wr, Wi, Ar, Ai,
                        4.16666667e-2f, 8.33333333e-3f);
        __syncthreads();
        // W = G1 + A2*W   (I/2 + A/6)
        cmm<true, true>(A2r, A2i, Wr, Wi, Wr, Wi, Ar, Ai, 0.5f, 1.f / 6.f);
        __syncthreads();
        // W = G0 + A2*W   (I + A)
        cmm<true, true>(A2r, A2i, Wr, Wi, Wr, Wi, Ar, Ai, 1.f, 1.f);
        __syncthreads();

        // ---- 7. 6 in-place squarings: W = exp(-iH/4) ----
#pragma unroll 1
        for (int q = 0; q < NSQ; q++) {
            cmm<false, true>(Wr, Wi, Wr, Wi, Wr, Wi, Ar, Ai, 0, 0);
            __syncthreads();
        }

        // ---- 8a. parameter job: publish Vp and signal ----
        if (is_param) {
            for (int idx = tid; idx < DIM * DIM; idx += NTHREADS) {
                const int i = idx >> 6, j = idx & 63;
                g_Up[job][idx] = make_float2(Wr[i * S + j], Wi[i * S + j]);
            }
            __threadfence();
            __syncthreads();
            if (tid == 0) atomicAdd(&g_flag, 1);
            continue;
        }

        // ---- 8b. data job: wait for all Vp, run circuit ----
        if (tid == 0) {
            int v;
            do {
                asm volatile("ld.global.acquire.gpu.b32 %0, [%1];"
                             : "=r"(v) : "l"(&g_flag));
                if (v < nreps) __nanosleep(64);
            } while (v < nreps);
        }
        if (tid < DIM) psiA[tid] = make_float2(tid == 0 ? 1.f : 0.f, 0.f);
        __syncthreads();

        // matvec layout: 512 threads = 64 rows x 8 partials
        float2* pin = psiA;
        float2* pout = psiB;
        const int row = tid >> 3, part = tid & 7;
        const int k0 = part * 8;

        for (int r = 0; r < 4; r++) {
            // Ud = Vd^4 : apply Vd (smem W planes) VAPP times
#pragma unroll 1
            for (int v = 0; v < VAPP; v++) {
                float sr = 0.f, si = 0.f;
#pragma unroll
                for (int k = k0; k < k0 + 8; k++) {
                    const float mr = Wr[row * S + k], mi = Wi[row * S + k];
                    const float2 w = pin[k];
                    sr = fmaf(mr, w.x, sr); sr = fmaf(-mi, w.y, sr);
                    si = fmaf(mr, w.y, si); si = fmaf(mi, w.x, si);
                }
                sr += __shfl_xor_sync(0xffffffffu, sr, 1);
                sr += __shfl_xor_sync(0xffffffffu, sr, 2);
                sr += __shfl_xor_sync(0xffffffffu, sr, 4);
                si += __shfl_xor_sync(0xffffffffu, si, 1);
                si += __shfl_xor_sync(0xffffffffu, si, 2);
                si += __shfl_xor_sync(0xffffffffu, si, 4);
                if (part == 0) pout[row] = make_float2(sr, si);
                __syncthreads();
                { float2* t = pin; pin = pout; pout = t; }
            }
            // Up[r] = Vp^4 : apply Vp (global, L2-hot) VAPP times
            const float2* U = g_Up[r];
#pragma unroll 1
            for (int v = 0; v < VAPP; v++) {
                float sr = 0.f, si = 0.f;
#pragma unroll
                for (int k = k0; k < k0 + 8; k++) {
                    const float2 u = U[row * DIM + k];
                    const float2 w = pin[k];
                    sr = fmaf(u.x, w.x, sr); sr = fmaf(-u.y, w.y, sr);
                    si = fmaf(u.x, w.y, si); si = fmaf(u.y, w.x, si);
                }
                sr += __shfl_xor_sync(0xffffffffu, sr, 1);
                sr += __shfl_xor_sync(0xffffffffu, sr, 2);
                sr += __shfl_xor_sync(0xffffffffu, sr, 4);
                si += __shfl_xor_sync(0xffffffffu, si, 1);
                si += __shfl_xor_sync(0xffffffffu, si, 2);
                si += __shfl_xor_sync(0xffffffffu, si, 4);
                if (part == 0) pout[row] = make_float2(sr, si);
                __syncthreads();
                { float2* t = pin; pin = pout; pout = t; }
            }
        }

        if (tid < DIM) {
            const float2 v = pin[tid];
            out[(size_t)(job - nreps) * DIM + tid] =
                fmaf(v.x, v.x, v.y * v.y) + bias[tid];
        }
    }
}

extern "C" void kernel_launch(void* const* d_in, const int* in_sizes, int n_in,
                              void* d_out, int out_size)
{
    const float* x      = (const float*)d_in[0];   // [512, 4000]
    const float* weight = (const float*)d_in[1];   // [4, 4095]
    const float* bias   = (const float*)d_in[2];   // [64]
    float* out = (float*)d_out;                    // [512, 64]

    const int B     = in_sizes[0] / 4000;
    const int nreps = in_sizes[1] / (NPAULI - 1);
    const int njobs = nreps + B;

    const size_t smem = (size_t)6 * PL * sizeof(float);   // 104,448 B
    cudaFuncSetAttribute(build_kernel,
                         cudaFuncAttributeMaxDynamicSharedMemorySize, (int)smem);

    reset_kernel<<<1, 1>>>();
    const int grid = (njobs < GRID) ? njobs : GRID;
    build_kernel<<<grid, NTHREADS, smem>>>(x, weight, bias, out, nreps, njobs);
}

// round 17
// speedup vs baseline: 1.7579x; 1.0810x over previous
#include <cuda_runtime.h>

// ---------------------------------------------------------------------------
// DataReUploadingLinear, Round 16:
//   = the 387us champion (R3 source) with EXACTLY ONE change:
//     deg-11/s=8 PS (13 cmms) -> deg-16/s=6 PS (12 cmms; verified R6/R8).
//   Champion cmm body (2x4 tile, float4 X loads), grid 516 non-persistent,
//   fused circuit via flag spin — all byte-identical.
// ---------------------------------------------------------------------------

#define DIM      64
#define NPAULI   4096
#define S        68                  // smem row stride (17 x float4, 16B-aligned)
#define PL       (64 * S)            // plane size in floats (4352)
#define NTHREADS 512
#define INV_SCALE (1.0f / 64.0f)     // 1 / 2^s, s = 6

typedef unsigned long long u64;

__device__ float2 g_Up[4][DIM * DIM];   // parameter unitaries [i*64+k]
__device__ int    g_flag;               // count of finished Up blocks

__device__ __forceinline__ u64 pk2(float lo, float hi) {
    u64 r; asm("mov.b64 %0, {%1, %2};" : "=l"(r) : "f"(lo), "f"(hi)); return r;
}
__device__ __forceinline__ u64 f2fma(u64 a, u64 b, u64 c) {
    u64 d; asm("fma.rn.f32x2 %0, %1, %2, %3;" : "=l"(d) : "l"(a), "l"(b), "l"(c));
    return d;
}
__device__ __forceinline__ u64 f2sub(u64 a, u64 b) {
    float al, ah, bl, bh;
    asm("mov.b64 {%0, %1}, %2;" : "=f"(al), "=f"(ah) : "l"(a));
    asm("mov.b64 {%0, %1}, %2;" : "=f"(bl), "=f"(bh) : "l"(b));
    return pk2(al - bl, ah - bh);
}

// Z = [G(A)] + X*Y, complex 64x64 in smem (separate re/im planes, stride S).
// G = c0*I + c1*A + c2*A2 + c3*A3 when WITHG. Thread tile 2 rows x 4 cols.
// (Champion R3 body, verbatim.)
template <bool WITHG>
__device__ __forceinline__ void cmm(
    const float* __restrict__ Xr, const float* __restrict__ Xi,
    const float* __restrict__ Yr, const float* __restrict__ Yi,
    float* __restrict__ Zr, float* __restrict__ Zi,
    const float* __restrict__ Ar, const float* __restrict__ Ai,
    const float* __restrict__ A2r, const float* __restrict__ A2i,
    const float* __restrict__ A3r, const float* __restrict__ A3i,
    float c0, float c1, float c2, float c3)
{
    const int tid = threadIdx.x;
    const int ty = tid >> 4, tx = tid & 15;
    const int i0 = ty * 2, j0 = tx * 4;

    u64 crp[2][2], crn[2][2], cim[2][2];
#pragma unroll
    for (int a = 0; a < 2; a++)
#pragma unroll
        for (int p = 0; p < 2; p++) {
            if (WITHG) {
                const int i = i0 + a, j = j0 + 2 * p;
                const int o0 = i * S + j, o1 = o0 + 1;
                float g0r = c1 * Ar[o0] + c2 * A2r[o0] + c3 * A3r[o0]
                          + ((i == j)     ? c0 : 0.f);
                float g1r = c1 * Ar[o1] + c2 * A2r[o1] + c3 * A3r[o1]
                          + ((i == j + 1) ? c0 : 0.f);
                float g0i = c1 * Ai[o0] + c2 * A2i[o0] + c3 * A3i[o0];
                float g1i = c1 * Ai[o1] + c2 * A2i[o1] + c3 * A3i[o1];
                crp[a][p] = pk2(g0r, g1r);
                cim[a][p] = pk2(g0i, g1i);
            } else {
                crp[a][p] = 0ull; cim[a][p] = 0ull;
            }
            crn[a][p] = 0ull;
        }

#pragma unroll 2
    for (int k4 = 0; k4 < 64; k4 += 4) {
        // X: LDS.128 over 4 consecutive k (broadcast within half-warp)
        float4 xr4[2], xi4[2];
#pragma unroll
        for (int a = 0; a < 2; a++) {
            xr4[a] = *(const float4*)&Xr[(i0 + a) * S + k4];
            xi4[a] = *(const float4*)&Xi[(i0 + a) * S + k4];
        }
#pragma unroll
        for (int kk = 0; kk < 4; kk++) {
            // Y row k4+kk: LDS.128 re + LDS.128 im, used as packed col pairs
            const ulonglong2 r2 = *(const ulonglong2*)&Yr[(k4 + kk) * S + j0];
            const ulonglong2 q2 = *(const ulonglong2*)&Yi[(k4 + kk) * S + j0];
            const u64 yr[2] = { r2.x, r2.y };
            const u64 yi[2] = { q2.x, q2.y };
#pragma unroll
            for (int a = 0; a < 2; a++) {
                const float xr = (kk == 0) ? xr4[a].x : (kk == 1) ? xr4[a].y
                               : (kk == 2) ? xr4[a].z : xr4[a].w;
                const float xi = (kk == 0) ? xi4[a].x : (kk == 1) ? xi4[a].y
                               : (kk == 2) ? xi4[a].z : xi4[a].w;
                const u64 xrr = pk2(xr, xr);
                const u64 xii = pk2(xi, xi);
#pragma unroll
                for (int p = 0; p < 2; p++) {
                    crp[a][p] = f2fma(xrr, yr[p], crp[a][p]);
                    crn[a][p] = f2fma(xii, yi[p], crn[a][p]);
                    cim[a][p] = f2fma(xrr, yi[p], cim[a][p]);
                    cim[a][p] = f2fma(xii, yr[p], cim[a][p]);
                }
            }
        }
    }

#pragma unroll
    for (int a = 0; a < 2; a++)
#pragma unroll
        for (int p = 0; p < 2; p++) {
            *(u64*)&Zr[(i0 + a) * S + j0 + 2 * p] = f2sub(crp[a][p], crn[a][p]);
            *(u64*)&Zi[(i0 + a) * S + j0 + 2 * p] = cim[a][p];
        }
}

__global__ void reset_kernel() { g_flag = 0; }

// blockIdx < nreps: build Up[blk] -> g_Up, release flag.
// else: build Ud for sample (blk - nreps), wait for flag, run circuit, out.
__global__ __launch_bounds__(NTHREADS)
void build_kernel(const float* __restrict__ x,
                  const float* __restrict__ weight,
                  const float* __restrict__ bias,
                  float* __restrict__ out,
                  int nreps)
{
    extern __shared__ float sm[];
    float* Ar  = sm + 0 * PL;  float* Ai  = sm + 1 * PL;
    float* A2r = sm + 2 * PL;  float* A2i = sm + 3 * PL;
    float* A3r = sm + 4 * PL;  float* A3i = sm + 5 * PL;
    float* A4r = sm + 6 * PL;  float* A4i = sm + 7 * PL;
    float* Br  = sm + 8 * PL;  float* Bi  = sm + 9 * PL;
    float* Cr  = sm + 10 * PL; float* Ci  = sm + 11 * PL;
    __shared__ float2 psiA[DIM], psiB[DIM];

    const int tid = threadIdx.x;
    const int blk = blockIdx.x;
    const bool is_param = (blk < nreps);

    // ---- 1. Pauli coefficients (padded to 4096) into Br[0..4095] ----
    if (is_param) {
        const float* wrow = weight + (size_t)blk * (NPAULI - 1);
        for (int p = tid; p < NPAULI; p += NTHREADS)
            Br[p] = (p == 0) ? 0.f : wrow[p - 1];      // identity excluded
    } else {
        const float* xrow = x + (size_t)(blk - nreps) * 4000;
        for (int p = tid; p < NPAULI; p += NTHREADS)
            Br[p] = (p < 4000) ? xrow[p] : 0.f;
    }
    __syncthreads();

    // ---- 2. D[m][t] = coef(p(m,t)) * (-i)^popc(t&m) ----
    for (int idx = tid; idx < NPAULI; idx += NTHREADS) {
        const int m = idx >> 6, t = idx & 63;
        const int mt = m ^ t;
        int p = 0;
#pragma unroll
        for (int k = 0; k < 6; k++)
            p |= (((mt >> k) & 1) << (2 * k)) | (((t >> k) & 1) << (2 * k + 1));
        const float v = Br[p];
        const int c = __popc(t & m) & 3;   // (-i)^c
        float re, im;
        switch (c) {
            case 0:  re =  v; im = 0.f; break;
            case 1:  re = 0.f; im = -v; break;
            case 2:  re = -v; im = 0.f; break;
            default: re = 0.f; im =  v; break;
        }
        Cr[idx] = re; Ci[idx] = im;
    }
    __syncthreads();

    // ---- 3. 64-pt WHT over t for each m ----
    for (int s = 0; s < 6; s++) {
        const int half = 1 << s;
        for (int n = tid; n < 2048; n += NTHREADS) {
            const int m = n >> 5, r = n & 31;
            const int t0 = ((r >> s) << (s + 1)) | (r & (half - 1));
            const int a0 = m * 64 + t0, a1 = a0 + half;
            const float ur = Cr[a0], ui = Ci[a0];
            const float vr = Cr[a1], vi = Ci[a1];
            Cr[a0] = ur + vr; Ci[a0] = ui + vi;
            Cr[a1] = ur - vr; Ci[a1] = ui - vi;
        }
        __syncthreads();
    }

    // ---- 4. A = -i*H/2^s :  H[i][i^m] = W[m][i] ----
    for (int idx = tid; idx < NPAULI; idx += NTHREADS) {
        const int m = idx >> 6, i = idx & 63;
        const int j = i ^ m;
        const float hr = Cr[m * 64 + i], hi = Ci[m * 64 + i];
        Ar[i * S + j] =  hi * INV_SCALE;   // -i*(hr+i*hi) = hi - i*hr
        Ai[i * S + j] = -hr * INV_SCALE;
    }
    __syncthreads();

    // ---- 5. powers A2, A3, A4 ----
    cmm<false>(Ar, Ai, Ar, Ai, A2r, A2i,
               Ar, Ai, A2r, A2i, A3r, A3i, 0, 0, 0, 0);
    __syncthreads();
    cmm<false>(Ar, Ai, A2r, A2i, A3r, A3i,
               Ar, Ai, A2r, A2i, A3r, A3i, 0, 0, 0, 0);
    __syncthreads();
    cmm<false>(A2r, A2i, A2r, A2i, A4r, A4i,
               Ar, Ai, A2r, A2i, A3r, A3i, 0, 0, 0, 0);
    __syncthreads();

    // ---- 6. degree-16 PS with A4 blocks (verified R6/R8) ----
    {   // B = G3 = I/12! + A/13! + A2/14! + A3/15! + A4/16!
        const float c0 = 2.08767570e-9f,  d1 = 1.60590438e-10f;
        const float d2 = 1.14707456e-11f, d3 = 7.64716373e-13f;
        const float d4 = 4.77947733e-14f;
        for (int idx = tid; idx < NPAULI; idx += NTHREADS) {
            const int i = idx >> 6, j = idx & 63;
            const int o = i * S + j;
            float gr = d1 * Ar[o] + d2 * A2r[o] + d3 * A3r[o] + d4 * A4r[o];
            float gi = d1 * Ai[o] + d2 * A2i[o] + d3 * A3i[o] + d4 * A4i[o];
            if (i == j) gr += c0;
            Br[o] = gr; Bi[o] = gi;
        }
    }
    __syncthreads();
    // C = G2 + A4*B   (I/8! + A/9! + A2/10! + A3/11!)
    cmm<true>(A4r, A4i, Br, Bi, Cr, Ci, Ar, Ai, A2r, A2i, A3r, A3i,
              2.48015873e-5f, 2.75573192e-6f, 2.75573192e-7f, 2.50521084e-8f);
    __syncthreads();
    // B = G1 + A4*C   (I/4! + A/5! + A2/6! + A3/7!)
    cmm<true>(A4r, A4i, Cr, Ci, Br, Bi, Ar, Ai, A2r, A2i, A3r, A3i,
              4.16666667e-2f, 8.33333333e-3f, 1.38888889e-3f, 1.98412698e-4f);
    __syncthreads();
    // C = G0 + A4*B   (I + A + A2/2 + A3/6)
    cmm<true>(A4r, A4i, Br, Bi, Cr, Ci, Ar, Ai, A2r, A2i, A3r, A3i,
              1.f, 1.f, 0.5f, 1.f / 6.f);
    __syncthreads();

    // ---- 7. 6 squarings, ping-pong C <-> B (even count -> ends in C) ----
    float *qr = Cr, *qi = Ci, *pr = Br, *pi = Bi;
#pragma unroll 1
    for (int q = 0; q < 6; q++) {
        cmm<false>(qr, qi, qr, qi, pr, pi,
                   Ar, Ai, A2r, A2i, A3r, A3i, 0, 0, 0, 0);
        __syncthreads();
        float* t;
        t = qr; qr = pr; pr = t;
        t = qi; qi = pi; pi = t;
    }

    // ---- 8a. parameter blocks: publish Up and signal ----
    if (is_param) {
        for (int idx = tid; idx < DIM * DIM; idx += NTHREADS) {
            const int i = idx >> 6, j = idx & 63;
            g_Up[blk][idx] = make_float2(qr[i * S + j], qi[i * S + j]);
        }
        __threadfence();               // release g_Up before flag bump
        __syncthreads();
        if (tid == 0) atomicAdd(&g_flag, 1);
        return;
    }

    // ---- 8b. data blocks: wait for all Up, then run circuit in-CTA ----
    if (tid == 0) {
        int v;
        do {
            asm volatile("ld.global.acquire.gpu.b32 %0, [%1];"
                         : "=r"(v) : "l"(&g_flag));
            if (v < nreps) __nanosleep(64);
        } while (v < nreps);
    }
    __threadfence();
    if (tid < DIM) psiA[tid] = make_float2(tid == 0 ? 1.f : 0.f, 0.f);
    __syncthreads();

    if (tid < 256) {
        float2* pin = psiA;
        float2* pout = psiB;
        const int row = tid >> 2, part = tid & 3;
        const int k0 = part * 16;

        for (int r = 0; r < nreps; r++) {
            {   // pout = Ud * pin   (Ud lives in smem planes qr/qi)
                float sr = 0.f, si = 0.f;
#pragma unroll
                for (int k = k0; k < k0 + 16; k++) {
                    const float mr = qr[row * S + k], mi = qi[row * S + k];
                    const float2 v = pin[k];
                    sr = fmaf(mr, v.x, sr); sr = fmaf(-mi, v.y, sr);
                    si = fmaf(mr, v.y, si); si = fmaf(mi, v.x, si);
                }
                sr += __shfl_xor_sync(0xffffffffu, sr, 1);
                sr += __shfl_xor_sync(0xffffffffu, sr, 2);
                si += __shfl_xor_sync(0xffffffffu, si, 1);
                si += __shfl_xor_sync(0xffffffffu, si, 2);
                if (part == 0) pout[row] = make_float2(sr, si);
            }
            __syncwarp();
            asm volatile("bar.sync 1, 256;" ::: "memory");
            { float2* t = pin; pin = pout; pout = t; }

            {   // pout = Up[r] * pin
                const float2* U = g_Up[r];
                float sr = 0.f, si = 0.f;
#pragma unroll
                for (int k = k0; k < k0 + 16; k++) {
                    const float2 u = U[row * DIM + k];
                    const float2 v = pin[k];
                    sr = fmaf(u.x, v.x, sr); sr = fmaf(-u.y, v.y, sr);
                    si = fmaf(u.x, v.y, si); si = fmaf(u.y, v.x, si);
                }
                sr += __shfl_xor_sync(0xffffffffu, sr, 1);
                sr += __shfl_xor_sync(0xffffffffu, sr, 2);
                si += __shfl_xor_sync(0xffffffffu, si, 1);
                si += __shfl_xor_sync(0xffffffffu, si, 2);
                if (part == 0) pout[row] = make_float2(sr, si);
            }
            __syncwarp();
            asm volatile("bar.sync 1, 256;" ::: "memory");
            { float2* t = pin; pin = pout; pout = t; }
        }

        if (tid < DIM) {
            const float2 v = pin[tid];
            out[(size_t)(blk - nreps) * DIM + tid] =
                fmaf(v.x, v.x, v.y * v.y) + bias[tid];
        }
    }
}

extern "C" void kernel_launch(void* const* d_in, const int* in_sizes, int n_in,
                              void* d_out, int out_size)
{
    const float* x      = (const float*)d_in[0];   // [512, 4000]
    const float* weight = (const float*)d_in[1];   // [4, 4095]
    const float* bias   = (const float*)d_in[2];   // [64]
    float* out = (float*)d_out;                    // [512, 64]

    const int B     = in_sizes[0] / 4000;
    const int nreps = in_sizes[1] / (NPAULI - 1);

    const size_t smem = (size_t)12 * PL * sizeof(float);   // 208,896 B
    cudaFuncSetAttribute(build_kernel,
                         cudaFuncAttributeMaxDynamicSharedMemorySize, (int)smem);

    reset_kernel<<<1, 1>>>();
    build_kernel<<<nreps + B, NTHREADS, smem>>>(x, weight, bias, out, nreps);
}